// round 3
// baseline (speedup 1.0000x reference)
#include <cuda_runtime.h>
#include <cstdint>

#define BB 16
#define SS 4096
#define FF 256
#define KK 512
#define PP 8
#define NITS 5
#define SCHUNKS 4
#define SCHUNK_PTS (SS / SCHUNKS)   // 1024

#define FIXSCALE 1099511627776.0    // 2^40

// ---------------- device scratch ----------------
static __device__ float g_cent[BB * KK * 3];                       // centroids
static __device__ unsigned long long g_isum[BB * KK * 3];          // fixed-point sums (exact, deterministic)
static __device__ int g_icnt[BB * KK];                             // exact counts
static __device__ unsigned long long g_part[(size_t)BB * KK * SCHUNKS * PP];

// ---------------- helpers ----------------
__device__ __forceinline__ unsigned float_ord(float f) {
    unsigned u = __float_as_uint(f);
    return (u & 0x80000000u) ? ~u : (u | 0x80000000u);
}

__device__ __forceinline__ unsigned long long umin64(unsigned long long a, unsigned long long b) {
    return a < b ? a : b;
}

// norm without FMA contraction: round(a0^2) + round(a1^2), rounded, + round(a2^2), rounded
// (mirrors jnp.sum(a*a, -1): elementwise multiply then sequential reduce)
__device__ __forceinline__ float norm3_nofma(float a0, float a1, float a2) {
    return __fadd_rn(__fadd_rn(__fmul_rn(a0, a0), __fmul_rn(a1, a1)), __fmul_rn(a2, a2));
}

// dot as ascending-d fma chain (mirrors XLA gemm accumulation for k=3)
__device__ __forceinline__ float dot3_fma(float a0, float a1, float a2,
                                          float b0, float b1, float b2) {
    return __fmaf_rn(a2, b2, __fmaf_rn(a1, b1, __fmul_rn(a0, b0)));
}

// d = (aa - 2*dot) + bb with the reference's left-assoc grouping.
// fma(-2,dot,aa) == aa - (2*dot) exactly (x2 is exact; single rounding either way).
__device__ __forceinline__ float sqdist_combine(float aa, float dot, float bb) {
    return __fadd_rn(__fmaf_rn(-2.0f, dot, aa), bb);
}

__device__ __forceinline__ void sort8_bitonic(unsigned long long v[8]) {
#define CSWP(i, j) { unsigned long long lo = umin64(v[i], v[j]); \
                     unsigned long long hi = (v[i] < v[j]) ? v[j] : v[i]; \
                     v[i] = lo; v[j] = hi; }
    CSWP(0, 4) CSWP(1, 5) CSWP(2, 6) CSWP(3, 7)
    CSWP(0, 2) CSWP(1, 3) CSWP(4, 6) CSWP(5, 7)
    CSWP(0, 1) CSWP(2, 3) CSWP(4, 5) CSWP(6, 7)
#undef CSWP
}

__device__ __forceinline__ void merge8(unsigned long long a[8], const unsigned long long b[8]) {
    unsigned long long m[8];
#pragma unroll
    for (int i = 0; i < 8; i++) m[i] = umin64(a[i], b[7 - i]);
    sort8_bitonic(m);
#pragma unroll
    for (int i = 0; i < 8; i++) a[i] = m[i];
}

// ---------------- kernels ----------------

__global__ void k_init(const float* __restrict__ pos) {
    int t = blockIdx.x * 256 + threadIdx.x;
    if (t >= BB * KK * 3) return;
    int b = t / (KK * 3);
    int r = t - b * (KK * 3);
    g_cent[(size_t)b * KK * 3 + r] = pos[(size_t)b * SS * 3 + r];
}

__global__ void k_zero() {
    int t = blockIdx.x * 256 + threadIdx.x;
    if (t >= BB * KK) return;
    g_icnt[t] = 0;
    g_isum[3 * t + 0] = 0ull;
    g_isum[3 * t + 1] = 0ull;
    g_isum[3 * t + 2] = 0ull;
}

// each thread = one point; smem = all 512 centroids (+ |c|^2, non-fma)
__global__ void k_assign(const float* __restrict__ pos) {
    __shared__ float4 sc[KK];
    int b = blockIdx.y;
    int s = blockIdx.x * 256 + threadIdx.x;
    const float* cb = g_cent + (size_t)b * KK * 3;
    for (int k = threadIdx.x; k < KK; k += 256) {
        float c0 = cb[3 * k], c1 = cb[3 * k + 1], c2 = cb[3 * k + 2];
        sc[k] = make_float4(c0, c1, c2, norm3_nofma(c0, c1, c2));
    }
    __syncthreads();

    const float* pp = pos + ((size_t)b * SS + s) * 3;
    float p0 = pp[0], p1 = pp[1], p2 = pp[2];
    float pn = norm3_nofma(p0, p1, p2);

    float best = __int_as_float(0x7f800000);  // +inf
    int bi = 0;
#pragma unroll 4
    for (int k = 0; k < KK; k++) {
        float4 c = sc[k];
        float dot = dot3_fma(p0, p1, p2, c.x, c.y, c.z);
        float v = sqdist_combine(pn, dot, c.w);
        if (v < best) { best = v; bi = k; }   // strict '<' == argmin first-index
    }
    // exact fixed-point accumulation: deterministic regardless of atomic order
    unsigned long long* sm = g_isum + ((size_t)b * KK + bi) * 3;
    atomicAdd(sm + 0, (unsigned long long)__double2ll_rn((double)p0 * FIXSCALE));
    atomicAdd(sm + 1, (unsigned long long)__double2ll_rn((double)p1 * FIXSCALE));
    atomicAdd(sm + 2, (unsigned long long)__double2ll_rn((double)p2 * FIXSCALE));
    atomicAdd(g_icnt + b * KK + bi, 1);
}

__global__ void k_update() {
    int t = blockIdx.x * 256 + threadIdx.x;
    if (t >= BB * KK) return;
    float cnt = (float)g_icnt[t];
    cnt = cnt > 1.0f ? cnt : 1.0f;           // jnp.maximum(counts, 1.0)
#pragma unroll
    for (int d = 0; d < 3; d++) {
        float sumf = (float)((double)g_isum[3 * t + d] * (1.0 / FIXSCALE));
        g_cent[3 * t + d] = __fdiv_rn(sumf, cnt);
    }
}

// partial top-8: block = (s-chunk, k-chunk of 128, b); thread = one centroid
__global__ void k_topk(const float* __restrict__ pos) {
    __shared__ float4 sp[SCHUNK_PTS];
    int b = blockIdx.z;
    int kbase = blockIdx.y * 128;
    int sbase = blockIdx.x * SCHUNK_PTS;

    for (int i = threadIdx.x; i < SCHUNK_PTS; i += 128) {
        const float* pp = pos + ((size_t)b * SS + sbase + i) * 3;
        float p0 = pp[0], p1 = pp[1], p2 = pp[2];
        sp[i] = make_float4(p0, p1, p2, norm3_nofma(p0, p1, p2));
    }
    __syncthreads();

    int k = kbase + threadIdx.x;
    const float* cb = g_cent + ((size_t)b * KK + k) * 3;
    float c0 = cb[0], c1 = cb[1], c2 = cb[2];
    float cn = norm3_nofma(c0, c1, c2);

    unsigned long long l[8];
#pragma unroll
    for (int j = 0; j < 8; j++) l[j] = 0xFFFFFFFFFFFFFFFFull;

#pragma unroll 4
    for (int i = 0; i < SCHUNK_PTS; i++) {
        float4 p = sp[i];
        float dot = dot3_fma(c0, c1, c2, p.x, p.y, p.z);
        float v = sqdist_combine(cn, dot, p.w);
        if (v == 0.0f) v = 0.0f;             // canonicalize -0.0 so ties follow index order
        unsigned long long key =
            ((unsigned long long)float_ord(v) << 32) | (unsigned)(sbase + i);
        if (key < l[7]) {
            l[7] = key;
#pragma unroll
            for (int j = 7; j > 0; --j) {
                if (l[j] < l[j - 1]) {
                    unsigned long long t = l[j]; l[j] = l[j - 1]; l[j - 1] = t;
                }
            }
        }
    }

    unsigned long long* outp =
        g_part + (((size_t)b * KK + k) * SCHUNKS + blockIdx.x) * 8;
#pragma unroll
    for (int j = 0; j < 8; j++) outp[j] = l[j];
}

// merge 4 partial lists per (b,k), then gather 8 rows of x and mean
__global__ void k_out(const float* __restrict__ x, float* __restrict__ out) {
    __shared__ int sidx[8];
    int bk = blockIdx.x;

    if (threadIdx.x == 0) {
        const unsigned long long* gp = g_part + (size_t)bk * SCHUNKS * 8;
        unsigned long long a[8], t[8];
#pragma unroll
        for (int j = 0; j < 8; j++) a[j] = gp[j];
#pragma unroll
        for (int c = 1; c < SCHUNKS; c++) {
#pragma unroll
            for (int j = 0; j < 8; j++) t[j] = gp[c * 8 + j];
            merge8(a, t);
        }
#pragma unroll
        for (int j = 0; j < 8; j++) sidx[j] = (int)(unsigned)a[j];
    }
    __syncthreads();

    int b = bk >> 9;  // / KK
    int f = threadIdx.x;
    float acc = 0.0f;
#pragma unroll
    for (int p = 0; p < 8; p++)
        acc += __ldg(&x[((size_t)b * SS + sidx[p]) * FF + f]);
    out[(size_t)bk * FF + f] = acc * 0.125f;
}

// ---------------- launch ----------------
extern "C" void kernel_launch(void* const* d_in, const int* in_sizes, int n_in,
                              void* d_out, int out_size) {
    const float* x   = (const float*)d_in[0];   // (B,S,F) f32
    const float* pos = (const float*)d_in[1];   // (B,S,D) f32
    float* out = (float*)d_out;                 // (B,K,F) f32
    (void)in_sizes; (void)n_in; (void)out_size;

    k_init<<<(BB * KK * 3 + 255) / 256, 256>>>(pos);
    for (int it = 0; it < NITS; it++) {
        k_zero<<<(BB * KK + 255) / 256, 256>>>();
        k_assign<<<dim3(SS / 256, BB), 256>>>(pos);
        k_update<<<(BB * KK + 255) / 256, 256>>>();
    }
    k_topk<<<dim3(SCHUNKS, KK / 128, BB), 128>>>(pos);
    k_out<<<BB * KK, FF>>>(x, out);
}

// round 4
// speedup vs baseline: 1.1546x; 1.1546x over previous
#include <cuda_runtime.h>
#include <cstdint>

#define BB 16
#define SS 4096
#define FF 256
#define KK 512
#define PP 8
#define NITS 5
#define GRID 128
#define THREADS 256
#define SCHUNKS 4
#define SCHUNK_PTS 1024
#define FIXSCALE 1099511627776.0   // 2^40

// ---------------- device scratch ----------------
static __device__ unsigned long long g_isum[3][BB * KK * 3];  // triple-buffered fixed-point sums
static __device__ int g_icnt[3][BB * KK];                     // triple-buffered counts
static __device__ unsigned long long g_part[(size_t)BB * KK * SCHUNKS * PP];
static __device__ unsigned g_bar_count = 0;
static __device__ unsigned g_bar_phase = 0;

// ---------------- FP helpers (byte-identical semantics to the passing kernel) --------
__device__ __forceinline__ unsigned float_ord(float f) {
    unsigned u = __float_as_uint(f);
    return (u & 0x80000000u) ? ~u : (u | 0x80000000u);
}
__device__ __forceinline__ float ord_inv(unsigned u) {
    return __uint_as_float((u & 0x80000000u) ? (u & 0x7FFFFFFFu) : ~u);
}
__device__ __forceinline__ unsigned long long umin64(unsigned long long a, unsigned long long b) {
    return a < b ? a : b;
}
// mirrors jnp.sum(a*a,-1): elementwise mul then sequential reduce (no FMA contraction)
__device__ __forceinline__ float norm3_nofma(float a0, float a1, float a2) {
    return __fadd_rn(__fadd_rn(__fmul_rn(a0, a0), __fmul_rn(a1, a1)), __fmul_rn(a2, a2));
}
// ascending-d fma chain
__device__ __forceinline__ float dot3_fma(float a0, float a1, float a2,
                                          float b0, float b1, float b2) {
    return __fmaf_rn(a2, b2, __fmaf_rn(a1, b1, __fmul_rn(a0, b0)));
}
// (aa - 2*dot) + bb, reference grouping
__device__ __forceinline__ float sqdist_combine(float aa, float dot, float bb) {
    return __fadd_rn(__fmaf_rn(-2.0f, dot, aa), bb);
}

__device__ __forceinline__ void sort8_bitonic(unsigned long long v[8]) {
#define CSWP(i, j) { unsigned long long lo = umin64(v[i], v[j]); \
                     unsigned long long hi = (v[i] < v[j]) ? v[j] : v[i]; \
                     v[i] = lo; v[j] = hi; }
    CSWP(0, 4) CSWP(1, 5) CSWP(2, 6) CSWP(3, 7)
    CSWP(0, 2) CSWP(1, 3) CSWP(4, 6) CSWP(5, 7)
    CSWP(0, 1) CSWP(2, 3) CSWP(4, 5) CSWP(6, 7)
#undef CSWP
}
__device__ __forceinline__ void merge8(unsigned long long a[8], const unsigned long long b[8]) {
    unsigned long long m[8];
#pragma unroll
    for (int i = 0; i < 8; i++) m[i] = umin64(a[i], b[7 - i]);
    sort8_bitonic(m);
#pragma unroll
    for (int i = 0; i < 8; i++) a[i] = m[i];
}

// ---------------- grid barrier (all GRID blocks co-resident: GRID=128 < 148 SMs) ----
__device__ __forceinline__ void grid_sync() {
    __syncthreads();
    if (threadIdx.x == 0) {
        __threadfence();
        unsigned gen = atomicAdd(&g_bar_phase, 0u);
        if (atomicAdd(&g_bar_count, 1u) == GRID - 1) {
            g_bar_count = 0;
            __threadfence();
            atomicAdd(&g_bar_phase, 1u);  // release
        } else {
            while (atomicAdd(&g_bar_phase, 0u) == gen) __nanosleep(64);
        }
        __threadfence();
    }
    __syncthreads();
}

// ---------------- megakernel ----------------
__global__ void __launch_bounds__(THREADS, 1)
mega(const float* __restrict__ x, const float* __restrict__ pos, float* __restrict__ out) {
    __shared__ float4 s4[SCHUNK_PTS];   // 16KB: centroids (assign) / staged points (topk)
    __shared__ int sidx[64][PP];        // 2KB:  merged indices (out)

    const int tid = threadIdx.x;
    const int blk = blockIdx.x;
    const int gtid = blk * THREADS + tid;

    // ---- init: zero buffer 1 (the W buffer of iteration 0) ----
    if (gtid < BB * KK) {
        g_icnt[1][gtid] = 0;
        g_isum[1][3 * gtid + 0] = 0ull;
        g_isum[1][3 * gtid + 1] = 0ull;
        g_isum[1][3 * gtid + 2] = 0ull;
    }
    grid_sync();

    // ---- k-means: 5 iterations, one barrier each ----
    const int b = blk >> 3;                 // batch (8 blocks per batch)
    const int sb = (blk & 7) * 512;         // point slice base
    const float* pbase = pos + ((size_t)b * SS + sb) * 3;

    for (int it = 0; it < NITS; it++) {
        const int Rb = it % 3;
        const int Wb = (it + 1) % 3;
        const int Zb = (it + 2) % 3;

        // build this batch's 512 centroids (+|c|^2) in smem
        for (int k = tid; k < KK; k += THREADS) {
            float c0, c1, c2;
            if (it == 0) {
                const float* cp = pos + ((size_t)b * SS + k) * 3;
                c0 = cp[0]; c1 = cp[1]; c2 = cp[2];
            } else {
                int slot = b * KK + k;
                float cnt = (float)g_icnt[Rb][slot];
                cnt = cnt > 1.0f ? cnt : 1.0f;
                c0 = __fdiv_rn((float)((double)(long long)g_isum[Rb][3 * slot + 0] * (1.0 / FIXSCALE)), cnt);
                c1 = __fdiv_rn((float)((double)(long long)g_isum[Rb][3 * slot + 1] * (1.0 / FIXSCALE)), cnt);
                c2 = __fdiv_rn((float)((double)(long long)g_isum[Rb][3 * slot + 2] * (1.0 / FIXSCALE)), cnt);
            }
            s4[k] = make_float4(c0, c1, c2, norm3_nofma(c0, c1, c2));
        }
        // zero this block's slice of the Z buffer (64 of 8192 slots)
        if (tid < 64) {
            int slot = blk * 64 + tid;
            g_icnt[Zb][slot] = 0;
            g_isum[Zb][3 * slot + 0] = 0ull;
            g_isum[Zb][3 * slot + 1] = 0ull;
            g_isum[Zb][3 * slot + 2] = 0ull;
        }
        __syncthreads();

        // assign: 2 points per thread
        float pA0 = pbase[3 * tid + 0], pA1 = pbase[3 * tid + 1], pA2 = pbase[3 * tid + 2];
        float pB0 = pbase[3 * (tid + 256) + 0], pB1 = pbase[3 * (tid + 256) + 1], pB2 = pbase[3 * (tid + 256) + 2];
        float pAn = norm3_nofma(pA0, pA1, pA2);
        float pBn = norm3_nofma(pB0, pB1, pB2);

        float bestA = __int_as_float(0x7f800000), bestB = bestA;
        int biA = 0, biB = 0;
#pragma unroll 8
        for (int k = 0; k < KK; k++) {
            float4 c = s4[k];
            float dA = dot3_fma(pA0, pA1, pA2, c.x, c.y, c.z);
            float dB = dot3_fma(pB0, pB1, pB2, c.x, c.y, c.z);
            float vA = sqdist_combine(pAn, dA, c.w);
            float vB = sqdist_combine(pBn, dB, c.w);
            if (vA < bestA) { bestA = vA; biA = k; }
            if (vB < bestB) { bestB = vB; biB = k; }
        }
        {
            unsigned long long* smA = &g_isum[Wb][((size_t)b * KK + biA) * 3];
            atomicAdd(smA + 0, (unsigned long long)__double2ll_rn((double)pA0 * FIXSCALE));
            atomicAdd(smA + 1, (unsigned long long)__double2ll_rn((double)pA1 * FIXSCALE));
            atomicAdd(smA + 2, (unsigned long long)__double2ll_rn((double)pA2 * FIXSCALE));
            atomicAdd(&g_icnt[Wb][b * KK + biA], 1);
            unsigned long long* smB = &g_isum[Wb][((size_t)b * KK + biB) * 3];
            atomicAdd(smB + 0, (unsigned long long)__double2ll_rn((double)pB0 * FIXSCALE));
            atomicAdd(smB + 1, (unsigned long long)__double2ll_rn((double)pB1 * FIXSCALE));
            atomicAdd(smB + 2, (unsigned long long)__double2ll_rn((double)pB2 * FIXSCALE));
            atomicAdd(&g_icnt[Wb][b * KK + biB], 1);
        }
        grid_sync();
    }

    // ---- top-8: final centroids live in accumulator buffer (NITS % 3) == 2 ----
    {
        const int FB = NITS % 3;            // = 2
        const int unit = blk & 7;           // 8 units per batch
        const int kc = unit >> 2;           // k-chunk: 0..1 (256 centroids each)
        const int sc_ = unit & 3;           // s-chunk: 0..3 (1024 points each)
        const int sbase = sc_ * SCHUNK_PTS;

        const int k = kc * 256 + tid;
        const int slot = b * KK + k;
        float cnt = (float)g_icnt[FB][slot];
        cnt = cnt > 1.0f ? cnt : 1.0f;
        float c0 = __fdiv_rn((float)((double)(long long)g_isum[FB][3 * slot + 0] * (1.0 / FIXSCALE)), cnt);
        float c1 = __fdiv_rn((float)((double)(long long)g_isum[FB][3 * slot + 1] * (1.0 / FIXSCALE)), cnt);
        float c2 = __fdiv_rn((float)((double)(long long)g_isum[FB][3 * slot + 2] * (1.0 / FIXSCALE)), cnt);
        float cn = norm3_nofma(c0, c1, c2);

        // stage 1024 points
        for (int i = tid; i < SCHUNK_PTS; i += THREADS) {
            const float* pp = pos + ((size_t)b * SS + sbase + i) * 3;
            float p0 = pp[0], p1 = pp[1], p2 = pp[2];
            s4[i] = make_float4(p0, p1, p2, norm3_nofma(p0, p1, p2));
        }
        __syncthreads();

        unsigned long long l[8];
#pragma unroll
        for (int j = 0; j < 8; j++) l[j] = 0xFF800000FFFFFFFFull;   // ord(+inf) | idx_max
        float thresh = __int_as_float(0x7f800000);                  // +inf

#pragma unroll 4
        for (int i = 0; i < SCHUNK_PTS; i++) {
            float4 p = s4[i];
            float dot = dot3_fma(c0, c1, c2, p.x, p.y, p.z);
            float v = sqdist_combine(cn, dot, p.w);
            // v < thresh  <=>  key < l[7]  (ascending indices; canon only changes -0)
            if (v < thresh) {
                float vc = (v == 0.0f) ? 0.0f : v;   // canonicalize -0.0
                unsigned long long key =
                    ((unsigned long long)float_ord(vc) << 32) | (unsigned)(sbase + i);
                l[7] = key;
#pragma unroll
                for (int j = 7; j > 0; --j) {
                    if (l[j] < l[j - 1]) {
                        unsigned long long t = l[j]; l[j] = l[j - 1]; l[j - 1] = t;
                    }
                }
                thresh = ord_inv((unsigned)(l[7] >> 32));
            }
        }
        unsigned long long* outp = g_part + ((size_t)slot * SCHUNKS + sc_) * PP;
#pragma unroll
        for (int j = 0; j < 8; j++) outp[j] = l[j];
    }
    grid_sync();

    // ---- merge + gather-mean: 64 (b,k) units per block ----
    if (tid < 64) {
        int bk = blk * 64 + tid;
        const unsigned long long* gp = g_part + (size_t)bk * SCHUNKS * PP;
        unsigned long long a[8], t[8];
#pragma unroll
        for (int j = 0; j < 8; j++) a[j] = gp[j];
#pragma unroll
        for (int c = 1; c < SCHUNKS; c++) {
#pragma unroll
            for (int j = 0; j < 8; j++) t[j] = gp[c * 8 + j];
            merge8(a, t);
        }
#pragma unroll
        for (int j = 0; j < 8; j++) sidx[tid][j] = (int)(unsigned)a[j];
    }
    __syncthreads();

    // gather: f = tid (FF == THREADS), coalesced
    const float* xb = x + (size_t)b * SS * FF;
    for (int u = 0; u < 64; u++) {
        float acc = 0.0f;
#pragma unroll
        for (int p = 0; p < 8; p++)
            acc += __ldg(&xb[(size_t)sidx[u][p] * FF + tid]);
        out[(size_t)(blk * 64 + u) * FF + tid] = acc * 0.125f;
    }
}

// ---------------- launch ----------------
extern "C" void kernel_launch(void* const* d_in, const int* in_sizes, int n_in,
                              void* d_out, int out_size) {
    const float* x   = (const float*)d_in[0];   // (B,S,F) f32
    const float* pos = (const float*)d_in[1];   // (B,S,D) f32
    float* out = (float*)d_out;                 // (B,K,F) f32
    (void)in_sizes; (void)n_in; (void)out_size;

    mega<<<GRID, THREADS>>>(x, pos, out);
}

// round 5
// speedup vs baseline: 1.1680x; 1.0116x over previous
#include <cuda_runtime.h>
#include <cstdint>

#define BB 16
#define SS 4096
#define FF 256
#define KK 512
#define PP 8
#define NITS 5
#define GRID 128
#define THREADS 512
#define NCHUNKS 8            // partial top-8 chunks per (b,k)
#define CHUNK_PTS 512        // points per chunk
#define FIXSCALE 1099511627776.0   // 2^40

// ---------------- device scratch ----------------
static __device__ unsigned long long g_isum[3][BB * KK * 3];  // triple-buffered fixed-point sums
static __device__ int g_icnt[3][BB * KK];                     // triple-buffered counts
static __device__ unsigned long long g_part[(size_t)BB * KK * NCHUNKS * PP];
static __device__ unsigned g_bar_count = 0;
static __device__ unsigned g_bar_phase = 0;

// ---------------- packed f32x2 helpers (per-lane rounding == scalar .rn) ----------
#define MUL2(out, a, b)    asm("mul.rn.f32x2 %0, %1, %2;"     : "=l"(out) : "l"(a), "l"(b))
#define ADD2(out, a, b)    asm("add.rn.f32x2 %0, %1, %2;"     : "=l"(out) : "l"(a), "l"(b))
#define FMA2(out, a, b, c) asm("fma.rn.f32x2 %0, %1, %2, %3;" : "=l"(out) : "l"(a), "l"(b), "l"(c))
#define PACK2(out, lo, hi) asm("mov.b64 %0, {%1, %2};" : "=l"(out) : "r"(__float_as_uint(lo)), "r"(__float_as_uint(hi)))
#define UNPACK2(lo, hi, in) { unsigned _ulo, _uhi; \
    asm("mov.b64 {%0, %1}, %2;" : "=r"(_ulo), "=r"(_uhi) : "l"(in)); \
    lo = __uint_as_float(_ulo); hi = __uint_as_float(_uhi); }

// ---------------- FP helpers (semantics identical to the passing kernel) --------
__device__ __forceinline__ unsigned float_ord(float f) {
    unsigned u = __float_as_uint(f);
    return (u & 0x80000000u) ? ~u : (u | 0x80000000u);
}
__device__ __forceinline__ float ord_inv(unsigned u) {
    return __uint_as_float((u & 0x80000000u) ? (u & 0x7FFFFFFFu) : ~u);
}
__device__ __forceinline__ unsigned long long umin64(unsigned long long a, unsigned long long b) {
    return a < b ? a : b;
}
// mirrors jnp.sum(a*a,-1): elementwise mul then sequential reduce (no FMA contraction)
__device__ __forceinline__ float norm3_nofma(float a0, float a1, float a2) {
    return __fadd_rn(__fadd_rn(__fmul_rn(a0, a0), __fmul_rn(a1, a1)), __fmul_rn(a2, a2));
}
// ascending-d fma chain
__device__ __forceinline__ float dot3_fma(float a0, float a1, float a2,
                                          float b0, float b1, float b2) {
    return __fmaf_rn(a2, b2, __fmaf_rn(a1, b1, __fmul_rn(a0, b0)));
}
// (aa - 2*dot) + bb, reference grouping
__device__ __forceinline__ float sqdist_combine(float aa, float dot, float bb) {
    return __fadd_rn(__fmaf_rn(-2.0f, dot, aa), bb);
}

__device__ __forceinline__ void sort8_bitonic(unsigned long long v[8]) {
#define CSWP(i, j) { unsigned long long lo = umin64(v[i], v[j]); \
                     unsigned long long hi = (v[i] < v[j]) ? v[j] : v[i]; \
                     v[i] = lo; v[j] = hi; }
    CSWP(0, 4) CSWP(1, 5) CSWP(2, 6) CSWP(3, 7)
    CSWP(0, 2) CSWP(1, 3) CSWP(4, 6) CSWP(5, 7)
    CSWP(0, 1) CSWP(2, 3) CSWP(4, 5) CSWP(6, 7)
#undef CSWP
}
__device__ __forceinline__ void merge8(unsigned long long a[8], const unsigned long long b[8]) {
    unsigned long long m[8];
#pragma unroll
    for (int i = 0; i < 8; i++) m[i] = umin64(a[i], b[7 - i]);
    sort8_bitonic(m);
#pragma unroll
    for (int i = 0; i < 8; i++) a[i] = m[i];
}

// ---------------- grid barrier (128 blocks < 148 SMs -> co-resident) ----
__device__ __forceinline__ void grid_sync() {
    __syncthreads();
    if (threadIdx.x == 0) {
        __threadfence();
        unsigned gen = atomicAdd(&g_bar_phase, 0u);
        if (atomicAdd(&g_bar_count, 1u) == GRID - 1) {
            g_bar_count = 0;
            __threadfence();
            atomicAdd(&g_bar_phase, 1u);  // release
        } else {
            while (atomicAdd(&g_bar_phase, 0u) == gen) __nanosleep(64);
        }
        __threadfence();
    }
    __syncthreads();
}

// ---------------- megakernel ----------------
__global__ void __launch_bounds__(THREADS, 1)
mega(const float* __restrict__ x, const float* __restrict__ pos, float* __restrict__ out) {
    // assign-phase centroid storage, pre-packed for f32x2:
    //   sA[k2] = { pack(c0[2k],c0[2k+1]), pack(c1[2k],c1[2k+1]) }
    //   sB[k2] = { pack(c2[2k],c2[2k+1]), pack(cn[2k],cn[2k+1]) }
    __shared__ ulonglong2 sA[KK / 2];     // 4KB
    __shared__ ulonglong2 sB[KK / 2];     // 4KB
    __shared__ float4 s4[1024];           // 16KB: staged points (topk)
    __shared__ int sidx[64][PP];          // 2KB: merged indices

    const int tid = threadIdx.x;
    const int blk = blockIdx.x;
    const int gtid = blk * THREADS + tid;
    const int b = blk >> 3;               // batch (8 blocks per batch)

    // ---- init: zero buffer 1 (W buffer of iteration 0) ----
    if (gtid < BB * KK) {
        g_icnt[1][gtid] = 0;
        g_isum[1][3 * gtid + 0] = 0ull;
        g_isum[1][3 * gtid + 1] = 0ull;
        g_isum[1][3 * gtid + 2] = 0ull;
    }
    grid_sync();

    // ---- k-means: 5 iterations, one barrier each ----
    // block handles 512 points: s = (blk&7)*512 + tid, one per thread
    const float* pp = pos + ((size_t)b * SS + (blk & 7) * 512 + tid) * 3;
    const float p0 = pp[0], p1 = pp[1], p2 = pp[2];
    const float pn = norm3_nofma(p0, p1, p2);

    unsigned long long px2, py2, pz2, pn2, neg2;
    PACK2(px2, p0, p0);
    PACK2(py2, p1, p1);
    PACK2(pz2, p2, p2);
    PACK2(pn2, pn, pn);
    PACK2(neg2, -2.0f, -2.0f);

    const unsigned long long addA =
        (unsigned long long)__double2ll_rn((double)p0 * FIXSCALE);
    const unsigned long long addB =
        (unsigned long long)__double2ll_rn((double)p1 * FIXSCALE);
    const unsigned long long addC =
        (unsigned long long)__double2ll_rn((double)p2 * FIXSCALE);

    for (int it = 0; it < NITS; it++) {
        const int Rb = it % 3;
        const int Wb = (it + 1) % 3;
        const int Zb = (it + 2) % 3;

        // build this batch's 512 centroids, packed (tid == k, exactly 512)
        {
            const int k = tid;
            float c0, c1, c2;
            if (it == 0) {
                const float* cp = pos + ((size_t)b * SS + k) * 3;
                c0 = cp[0]; c1 = cp[1]; c2 = cp[2];
            } else {
                int slot = b * KK + k;
                float cnt = (float)g_icnt[Rb][slot];
                cnt = cnt > 1.0f ? cnt : 1.0f;
                c0 = __fdiv_rn((float)((double)(long long)g_isum[Rb][3 * slot + 0] * (1.0 / FIXSCALE)), cnt);
                c1 = __fdiv_rn((float)((double)(long long)g_isum[Rb][3 * slot + 1] * (1.0 / FIXSCALE)), cnt);
                c2 = __fdiv_rn((float)((double)(long long)g_isum[Rb][3 * slot + 2] * (1.0 / FIXSCALE)), cnt);
            }
            float cn = norm3_nofma(c0, c1, c2);
            const int k2 = k >> 1, h = k & 1;
            float* a = (float*)&sA[k2];
            float* bp = (float*)&sB[k2];
            a[h] = c0; a[2 + h] = c1;
            bp[h] = c2; bp[2 + h] = cn;
        }
        // zero this block's slice of the Z buffer
        if (tid < 64) {
            int slot = blk * 64 + tid;
            g_icnt[Zb][slot] = 0;
            g_isum[Zb][3 * slot + 0] = 0ull;
            g_isum[Zb][3 * slot + 1] = 0ull;
            g_isum[Zb][3 * slot + 2] = 0ull;
        }
        __syncthreads();

        // assign: packed 2-centroid distance chain
        float best = __int_as_float(0x7f800000);
        int bi = 0;
#pragma unroll 8
        for (int k2 = 0; k2 < KK / 2; k2++) {
            ulonglong2 A = sA[k2];    // xx, yy
            ulonglong2 Bv = sB[k2];   // zz, nn
            unsigned long long dot2, t2, v2;
            MUL2(dot2, px2, A.x);
            FMA2(dot2, py2, A.y, dot2);
            FMA2(dot2, pz2, Bv.x, dot2);
            FMA2(t2, neg2, dot2, pn2);
            ADD2(v2, t2, Bv.y);
            float vlo, vhi;
            UNPACK2(vlo, vhi, v2);
            if (vlo < best) { best = vlo; bi = 2 * k2; }
            if (vhi < best) { best = vhi; bi = 2 * k2 + 1; }
        }
        {
            unsigned long long* sm = &g_isum[Wb][((size_t)b * KK + bi) * 3];
            atomicAdd(sm + 0, addA);
            atomicAdd(sm + 1, addB);
            atomicAdd(sm + 2, addC);
            atomicAdd(&g_icnt[Wb][b * KK + bi], 1);
        }
        grid_sync();
    }

    // ---- top-8: final centroids live in buffer (NITS % 3) == 2 ----
    {
        const int FB = NITS % 3;
        const int unit = blk & 7;
        const int kc = unit >> 2;             // 0..1: which 256 centroids
        const int sc_ = unit & 3;             // 0..3: which 1024-point chunk
        const int shalf = tid >> 8;           // 0..1: which 512-point half
        const int k = kc * 256 + (tid & 255);
        const int chunk = sc_ * 2 + shalf;    // 0..7
        const int sbase = sc_ * 1024 + shalf * CHUNK_PTS;

        const int slot = b * KK + k;
        float cnt = (float)g_icnt[FB][slot];
        cnt = cnt > 1.0f ? cnt : 1.0f;
        float c0 = __fdiv_rn((float)((double)(long long)g_isum[FB][3 * slot + 0] * (1.0 / FIXSCALE)), cnt);
        float c1 = __fdiv_rn((float)((double)(long long)g_isum[FB][3 * slot + 1] * (1.0 / FIXSCALE)), cnt);
        float c2 = __fdiv_rn((float)((double)(long long)g_isum[FB][3 * slot + 2] * (1.0 / FIXSCALE)), cnt);
        float cn = norm3_nofma(c0, c1, c2);

        // stage the block's 1024-point chunk
        for (int i = tid; i < 1024; i += THREADS) {
            const float* qp = pos + ((size_t)b * SS + sc_ * 1024 + i) * 3;
            float q0 = qp[0], q1 = qp[1], q2 = qp[2];
            s4[i] = make_float4(q0, q1, q2, norm3_nofma(q0, q1, q2));
        }
        __syncthreads();

        unsigned long long l[8];
#pragma unroll
        for (int j = 0; j < 8; j++) l[j] = 0xFF800000FFFFFFFFull;   // ord(+inf) | idx_max
        float thresh = __int_as_float(0x7f800000);

        const int ibase = shalf * CHUNK_PTS;
#pragma unroll 4
        for (int i = 0; i < CHUNK_PTS; i++) {
            float4 p = s4[ibase + i];
            float dot = dot3_fma(c0, c1, c2, p.x, p.y, p.z);
            float v = sqdist_combine(cn, dot, p.w);
            if (v < thresh) {
                float vc = (v == 0.0f) ? 0.0f : v;   // canonicalize -0.0
                unsigned long long key =
                    ((unsigned long long)float_ord(vc) << 32) | (unsigned)(sbase + i);
                l[7] = key;
#pragma unroll
                for (int j = 7; j > 0; --j) {
                    if (l[j] < l[j - 1]) {
                        unsigned long long t = l[j]; l[j] = l[j - 1]; l[j - 1] = t;
                    }
                }
                thresh = ord_inv((unsigned)(l[7] >> 32));
            }
        }
        unsigned long long* outp = g_part + ((size_t)slot * NCHUNKS + chunk) * PP;
#pragma unroll
        for (int j = 0; j < 8; j++) outp[j] = l[j];
    }
    grid_sync();

    // ---- merge + gather-mean: 64 (b,k) units per block ----
    if (tid < 64) {
        int bk = blk * 64 + tid;
        const unsigned long long* gp = g_part + (size_t)bk * NCHUNKS * PP;
        unsigned long long a[8], t[8];
#pragma unroll
        for (int j = 0; j < 8; j++) a[j] = gp[j];
#pragma unroll
        for (int c = 1; c < NCHUNKS; c++) {
#pragma unroll
            for (int j = 0; j < 8; j++) t[j] = gp[c * 8 + j];
            merge8(a, t);
        }
#pragma unroll
        for (int j = 0; j < 8; j++) sidx[tid][j] = (int)(unsigned)a[j];
    }
    __syncthreads();

    // gather: f = tid&255, two units in flight (tid>>8)
    {
        const float* xb = x + (size_t)b * SS * FF;
        const int f = tid & 255;
        const int uoff = tid >> 8;
        for (int uu = 0; uu < 32; uu++) {
            int u = uu * 2 + uoff;
            float acc = 0.0f;
#pragma unroll
            for (int p = 0; p < 8; p++)
                acc += __ldg(&xb[(size_t)sidx[u][p] * FF + f]);
            out[(size_t)(blk * 64 + u) * FF + f] = acc * 0.125f;
        }
    }
}

// ---------------- launch ----------------
extern "C" void kernel_launch(void* const* d_in, const int* in_sizes, int n_in,
                              void* d_out, int out_size) {
    const float* x   = (const float*)d_in[0];   // (B,S,F) f32
    const float* pos = (const float*)d_in[1];   // (B,S,D) f32
    float* out = (float*)d_out;                 // (B,K,F) f32
    (void)in_sizes; (void)n_in; (void)out_size;

    mega<<<GRID, THREADS>>>(x, pos, out);
}